// round 9
// baseline (speedup 1.0000x reference)
#include <cuda_runtime.h>
#include <cstdint>
#include <cstddef>

#define N_SIMP 8192
#define KF 8
#define BATCH 64
#define FEAT 128

// ---- kernel 1 tiling: wL = W @ L ----
#define SEG1 64                    // row segments (partial slices)
#define ROWS1 (N_SIMP / SEG1)      // 128 rows per segment
#define COLB1 16                   // column blocks
#define COLS1 (N_SIMP / COLB1)     // 512 cols per block = 128 thr * 4
// grid = 16 x 64 = 1024 CTAs -> 6.92 waves of 148 (tail ~1%)

// ---- kernel 2 tiling: out = wL @ x[b] ----
#define SEG2 16                    // n segments
#define ROWS2 (N_SIMP / SEG2)      // 512 n per segment
// grid = 64 x 16 = 1024 CTAs

typedef unsigned long long ull;

// Scratch (device globals: allocation-free rule)
__device__ float g_wL_part[SEG1][KF][N_SIMP];          // 16 MB
__device__ float g_wL[KF][N_SIMP];                     // 256 KB
__device__ float g_acc_part[SEG2][KF][BATCH][FEAT];    // 4 MB

__device__ __forceinline__ ull pack_dup(float a) {
    ull r; asm("mov.b64 %0, {%1, %1};" : "=l"(r) : "f"(a)); return r;
}
__device__ __forceinline__ void fma2(ull& d, ull a, ull b) {
    // packed f32x2 FMA: d = a*b + d on both halves (FFMA2 in SASS)
    asm("fma.rn.f32x2 %0, %1, %2, %0;" : "+l"(d) : "l"(a), "l"(b));
}
__device__ __forceinline__ float2 unpack2(ull v) {
    float2 r; asm("mov.b64 {%0, %1}, %2;" : "=f"(r.x), "=f"(r.y) : "l"(v)); return r;
}

// ============================================================
// k1: partial wL. Block = (colb, seg), 1024 CTAs.
// Thread owns 4 contiguous L columns, all 8 filters (4 k-pairs).
// Double-buffered 8-row blocks -> sustained MLP ~8.
// ============================================================
__device__ __forceinline__ void k1_compute8(const float4* lv, int mbase,
                                            ull acc[4][4],
                                            const float2 wtp[4][ROWS1]) {
    #pragma unroll
    for (int r = 0; r < 8; r++) {
        ull ld[4] = { pack_dup(lv[r].x), pack_dup(lv[r].y),
                      pack_dup(lv[r].z), pack_dup(lv[r].w) };
        #pragma unroll
        for (int kp = 0; kp < 4; kp++) {
            ull wp = *reinterpret_cast<const ull*>(&wtp[kp][mbase + r]);  // LDS.64 bcast
            #pragma unroll
            for (int j = 0; j < 4; j++) fma2(acc[kp][j], ld[j], wp);
        }
    }
}

__global__ __launch_bounds__(128, 1) void k1_wl(const float* __restrict__ W,
                                                const float* __restrict__ L) {
    const int tid  = threadIdx.x;
    const int colb = blockIdx.x;
    const int seg  = blockIdx.y;
    const int c0   = colb * COLS1 + tid * 4;
    const int m0   = seg * ROWS1;

    __shared__ float2 wtp[4][ROWS1];   // 4 KB, W segment as k-pairs
    for (int idx = tid; idx < 4 * ROWS1; idx += 128) {
        int kp = idx / ROWS1;
        int m  = idx % ROWS1;
        wtp[kp][m] = make_float2(W[(2 * kp) * N_SIMP + m0 + m],
                                 W[(2 * kp + 1) * N_SIMP + m0 + m]);
    }
    __syncthreads();

    ull acc[4][4];
    #pragma unroll
    for (int kp = 0; kp < 4; kp++)
        #pragma unroll
        for (int j = 0; j < 4; j++) acc[kp][j] = 0ULL;

    const float* Lp = L + (size_t)m0 * N_SIMP + c0;

    float4 bufA[8], bufB[8];
    #pragma unroll
    for (int r = 0; r < 8; r++)
        bufA[r] = __ldcs(reinterpret_cast<const float4*>(Lp + (size_t)r * N_SIMP));

    for (int m = 0; m < ROWS1; m += 16) {
        #pragma unroll
        for (int r = 0; r < 8; r++)
            bufB[r] = __ldcs(reinterpret_cast<const float4*>(
                          Lp + (size_t)(m + 8 + r) * N_SIMP));
        k1_compute8(bufA, m, acc, wtp);
        if (m + 16 < ROWS1) {
            #pragma unroll
            for (int r = 0; r < 8; r++)
                bufA[r] = __ldcs(reinterpret_cast<const float4*>(
                              Lp + (size_t)(m + 16 + r) * N_SIMP));
        }
        k1_compute8(bufB, m + 8, acc, wtp);
    }

    #pragma unroll
    for (int kp = 0; kp < 4; kp++) {
        float2 v0 = unpack2(acc[kp][0]);
        float2 v1 = unpack2(acc[kp][1]);
        float2 v2 = unpack2(acc[kp][2]);
        float2 v3 = unpack2(acc[kp][3]);
        float4 lo = make_float4(v0.x, v1.x, v2.x, v3.x);
        float4 hi = make_float4(v0.y, v1.y, v2.y, v3.y);
        __stcs(reinterpret_cast<float4*>(&g_wL_part[seg][2 * kp][c0]),     lo);
        __stcs(reinterpret_cast<float4*>(&g_wL_part[seg][2 * kp + 1][c0]), hi);
    }
}

// ============================================================
// k1b: reduce 64 partial segments into g_wL.
// float2 granularity: 32768 threads, 8-deep load batches.
// ============================================================
__global__ __launch_bounds__(128, 1) void k1_reduce() {
    int i = blockIdx.x * 128 + threadIdx.x;           // float2 index, 32768 total
    const float2* base = reinterpret_cast<const float2*>(&g_wL_part[0][0][0]);
    const int seg_stride = KF * N_SIMP / 2;           // 32768 float2 per segment
    float2 s = make_float2(0.f, 0.f);
    #pragma unroll
    for (int pb = 0; pb < SEG1; pb += 8) {
        float2 v[8];
        #pragma unroll
        for (int r = 0; r < 8; r++)
            v[r] = __ldcs(&base[(size_t)(pb + r) * seg_stride + i]);
        #pragma unroll
        for (int r = 0; r < 8; r++) { s.x += v[r].x; s.y += v[r].y; }
    }
    reinterpret_cast<float2*>(&g_wL[0][0])[i] = s;
}

// ============================================================
// k2: partial out accumulation. Block = (batch b, n segment), 1024 CTAs.
// 128 threads = 32 f-groups (float4 over FEAT) x 4 n-subgroups.
// Double-buffered 8-row blocks (stride 32 rows) -> sustained MLP ~8.
// Epilogue: smem tree-reduce over n-subgroups -> one slice per CTA.
// ============================================================
__device__ __forceinline__ void k2_compute8(const float4* xv, int nb, int ng,
                                            ull acc[4][4],
                                            const float2 wlp[4][ROWS2]) {
    #pragma unroll
    for (int r = 0; r < 8; r++) {
        int n = nb + ng + 4 * r;
        ull xd[4] = { pack_dup(xv[r].x), pack_dup(xv[r].y),
                      pack_dup(xv[r].z), pack_dup(xv[r].w) };
        #pragma unroll
        for (int kp = 0; kp < 4; kp++) {
            ull wp = *reinterpret_cast<const ull*>(&wlp[kp][n]);   // LDS.64 bcast
            #pragma unroll
            for (int j = 0; j < 4; j++) fma2(acc[kp][j], xd[j], wp);
        }
    }
}

__global__ __launch_bounds__(128, 1) void k2_out(const float* __restrict__ x) {
    const int tid = threadIdx.x;
    const int fg  = tid & 31;
    const int ng  = tid >> 5;
    const int b   = blockIdx.x;
    const int seg = blockIdx.y;
    const int n0  = seg * ROWS2;

    __shared__ float2 wlp[4][ROWS2];   // 16 KB, k-pairs of wL for this segment
    for (int idx = tid; idx < 4 * ROWS2; idx += 128) {
        int kp = idx >> 9;
        int n  = idx & (ROWS2 - 1);
        wlp[kp][n] = make_float2(g_wL[2 * kp][n0 + n], g_wL[2 * kp + 1][n0 + n]);
    }
    __syncthreads();

    ull acc[4][4];
    #pragma unroll
    for (int kp = 0; kp < 4; kp++)
        #pragma unroll
        for (int j = 0; j < 4; j++) acc[kp][j] = 0ULL;

    const float* xb = x + ((size_t)b * N_SIMP + n0) * FEAT + fg * 4;

    float4 bufA[8], bufB[8];
    #pragma unroll
    for (int r = 0; r < 8; r++)
        bufA[r] = __ldcs(reinterpret_cast<const float4*>(
                      xb + (size_t)(ng + 4 * r) * FEAT));

    for (int nb = 0; nb < ROWS2; nb += 64) {
        #pragma unroll
        for (int r = 0; r < 8; r++)
            bufB[r] = __ldcs(reinterpret_cast<const float4*>(
                          xb + (size_t)(nb + 32 + ng + 4 * r) * FEAT));
        k2_compute8(bufA, nb, ng, acc, wlp);
        if (nb + 64 < ROWS2) {
            #pragma unroll
            for (int r = 0; r < 8; r++)
                bufA[r] = __ldcs(reinterpret_cast<const float4*>(
                              xb + (size_t)(nb + 64 + ng + 4 * r) * FEAT));
        }
        k2_compute8(bufB, nb + 32, ng, acc, wlp);
    }

    // ---- epilogue: reduce over the 4 n-subgroups via smem (2 rounds) ----
    // Buffer: 2 src-groups x 32 fg x 32 floats = 8 KB, overlaid on wlp.
    __syncthreads();
    float (*rbuf)[32][32] = reinterpret_cast<float (*)[32][32]>(&wlp[0][0]);

    float mine[32];
    #pragma unroll
    for (int kp = 0; kp < 4; kp++) {
        #pragma unroll
        for (int j = 0; j < 4; j++) {
            float2 v = unpack2(acc[kp][j]);
            mine[(2 * kp) * 4 + j]     = v.x;
            mine[(2 * kp + 1) * 4 + j] = v.y;
        }
    }

    if (ng >= 2) {
        #pragma unroll
        for (int t = 0; t < 32; t++) rbuf[ng - 2][fg][t] = mine[t];
    }
    __syncthreads();
    if (ng < 2) {
        #pragma unroll
        for (int t = 0; t < 32; t++) mine[t] += rbuf[ng][fg][t];
    }
    __syncthreads();
    if (ng == 1) {
        #pragma unroll
        for (int t = 0; t < 32; t++) rbuf[0][fg][t] = mine[t];
    }
    __syncthreads();
    if (ng == 0) {
        #pragma unroll
        for (int k = 0; k < 8; k++) {
            float4 o = make_float4(mine[k * 4 + 0] + rbuf[0][fg][k * 4 + 0],
                                   mine[k * 4 + 1] + rbuf[0][fg][k * 4 + 1],
                                   mine[k * 4 + 2] + rbuf[0][fg][k * 4 + 2],
                                   mine[k * 4 + 3] + rbuf[0][fg][k * 4 + 3]);
            __stcs(reinterpret_cast<float4*>(&g_acc_part[seg][k][b][fg * 4]), o);
        }
    }
}

// ============================================================
// k3: reduce 16 partials + tanh -> out [K, B, F]. 32768 float2 threads.
// ============================================================
__global__ __launch_bounds__(128, 1) void k3_tanh(float* __restrict__ out) {
    int i = blockIdx.x * 128 + threadIdx.x;           // float2 index, 32768 total
    const float2* base = reinterpret_cast<const float2*>(&g_acc_part[0][0][0][0]);
    const int part_stride = KF * BATCH * FEAT / 2;    // 32768 float2 per partial
    float2 s = make_float2(0.f, 0.f);
    #pragma unroll
    for (int pb = 0; pb < SEG2; pb += 8) {
        float2 v[8];
        #pragma unroll
        for (int r = 0; r < 8; r++)
            v[r] = __ldcs(&base[(size_t)(pb + r) * part_stride + i]);
        #pragma unroll
        for (int r = 0; r < 8; r++) { s.x += v[r].x; s.y += v[r].y; }
    }
    reinterpret_cast<float2*>(out)[i] = make_float2(tanhf(s.x), tanhf(s.y));
}

// ============================================================
extern "C" void kernel_launch(void* const* d_in, const int* in_sizes, int n_in,
                              void* d_out, int out_size) {
    const float* x = (const float*)d_in[0];   // [B, N, F]
    const float* L = (const float*)d_in[1];   // [N, N]
    const float* W = (const float*)d_in[2];   // [K, N]
    float* out = (float*)d_out;               // [K, B, F]

    k1_wl<<<dim3(COLB1, SEG1), 128>>>(W, L);
    k1_reduce<<<256, 128>>>();
    k2_out<<<dim3(BATCH, SEG2), 128>>>(x);
    k3_tanh<<<256, 128>>>(out);
}

// round 10
// speedup vs baseline: 1.0231x; 1.0231x over previous
#include <cuda_runtime.h>
#include <cstdint>
#include <cstddef>

#define N_SIMP 8192
#define KF 8
#define BATCH 64
#define FEAT 128

// ---- kernel 1 tiling: wL = W @ L ----
#define SEG1 16                    // row segments (partial slices)
#define ROWS1 (N_SIMP / SEG1)      // 512 rows per segment
#define COLB1 16                   // column blocks
#define COLS1 (N_SIMP / COLB1)     // 512 cols per block = 128 thr * 4
#define S1 4                       // rows per pipeline stage (8 KB)
#define NST1 (ROWS1 / S1)          // 128 stages
// grid 16x16 = 256 CTAs, all resident (4 CTAs/SM x 148)

// ---- kernel 2 tiling: out = wL @ x[b] ----
#define SEG2 8                     // n segments
#define ROWS2 (N_SIMP / SEG2)      // 1024 n per segment
#define S2 8                       // rows per pipeline stage (4 KB)
#define NST2 (ROWS2 / S2)          // 128 stages
// grid 64x8 = 512 CTAs, all resident

#define DEPTH 4                    // pipeline stages in smem

typedef unsigned long long ull;

// Scratch (device globals: allocation-free rule)
__device__ float g_wL_part[SEG1][KF][N_SIMP];          // 4 MB
__device__ float g_wL[KF][N_SIMP];                     // 256 KB
__device__ float g_acc_part[SEG2][KF][BATCH][FEAT];    // 2 MB

__device__ __forceinline__ ull pack_dup(float a) {
    ull r; asm("mov.b64 %0, {%1, %1};" : "=l"(r) : "f"(a)); return r;
}
__device__ __forceinline__ void fma2(ull& d, ull a, ull b) {
    // packed f32x2 FMA: d = a*b + d on both halves (FFMA2 in SASS)
    asm("fma.rn.f32x2 %0, %1, %2, %0;" : "+l"(d) : "l"(a), "l"(b));
}
__device__ __forceinline__ float2 unpack2(ull v) {
    float2 r; asm("mov.b64 {%0, %1}, %2;" : "=f"(r.x), "=f"(r.y) : "l"(v)); return r;
}
__device__ __forceinline__ uint32_t smem_u32(const void* p) {
    return (uint32_t)__cvta_generic_to_shared(p);
}
__device__ __forceinline__ void cp16(uint32_t dst, const void* src) {
    asm volatile("cp.async.cg.shared.global [%0], [%1], 16;"
                 :: "r"(dst), "l"(src));
}
#define CP_COMMIT() asm volatile("cp.async.commit_group;")
#define CP_WAIT2()  asm volatile("cp.async.wait_group 2;")

// ============================================================
// k1: partial wL = W_seg @ L_seg. Block = (colb, seg), 256 CTAs.
// cp.async 4-stage pipeline: stage = 4 L rows x 2 KB (CTA's 512 cols).
// Thread owns 4 contiguous L columns (LDS.128 from stage), 8 filters.
// ============================================================
__global__ __launch_bounds__(128, 4) void k1_wl(const float* __restrict__ W,
                                                const float* __restrict__ L) {
    const int tid  = threadIdx.x;
    const int colb = blockIdx.x;
    const int seg  = blockIdx.y;
    const int c0   = colb * COLS1;
    const int m0   = seg * ROWS1;

    __shared__ float2 wtp[4][ROWS1];           // 16 KB, W segment as k-pairs
    __shared__ float4 stg[DEPTH][S1 * 128];    // 32 KB (4 stages x 8 KB)

    for (int idx = tid; idx < 4 * ROWS1; idx += 128) {
        int kp = idx >> 9;
        int m  = idx & (ROWS1 - 1);
        wtp[kp][m] = make_float2(W[(2 * kp) * N_SIMP + m0 + m],
                                 W[(2 * kp + 1) * N_SIMP + m0 + m]);
    }

    const float*   Lbase = L + (size_t)m0 * N_SIMP + c0 + tid * 4;
    const uint32_t stg0  = smem_u32(&stg[0][0]);

    auto issue = [&](int s) {
        if (s < NST1) {
            int buf = s & (DEPTH - 1);
            uint32_t d = stg0 + buf * (S1 * 2048) + tid * 16;
            const float* g = Lbase + (size_t)s * S1 * N_SIMP;
            #pragma unroll
            for (int r = 0; r < S1; r++)
                cp16(d + r * 2048, g + (size_t)r * N_SIMP);
        }
        CP_COMMIT();
    };

    issue(0); issue(1); issue(2);

    ull acc[4][4];
    #pragma unroll
    for (int kp = 0; kp < 4; kp++)
        #pragma unroll
        for (int j = 0; j < 4; j++) acc[kp][j] = 0ULL;

    for (int s = 0; s < NST1; s++) {
        CP_WAIT2();
        __syncthreads();
        issue(s + DEPTH - 1);
        const int buf = s & (DEPTH - 1);
        #pragma unroll
        for (int r = 0; r < S1; r++) {
            float4 lv = stg[buf][r * 128 + tid];   // LDS.128, conflict-free
            ull ld[4] = { pack_dup(lv.x), pack_dup(lv.y),
                          pack_dup(lv.z), pack_dup(lv.w) };
            const int m = s * S1 + r;
            #pragma unroll
            for (int kp = 0; kp < 4; kp++) {
                ull wp = *reinterpret_cast<const ull*>(&wtp[kp][m]);  // LDS.64 bcast
                #pragma unroll
                for (int j = 0; j < 4; j++) fma2(acc[kp][j], ld[j], wp);
            }
        }
    }

    const int cw = c0 + tid * 4;
    #pragma unroll
    for (int kp = 0; kp < 4; kp++) {
        float2 v0 = unpack2(acc[kp][0]);
        float2 v1 = unpack2(acc[kp][1]);
        float2 v2 = unpack2(acc[kp][2]);
        float2 v3 = unpack2(acc[kp][3]);
        float4 lo = make_float4(v0.x, v1.x, v2.x, v3.x);
        float4 hi = make_float4(v0.y, v1.y, v2.y, v3.y);
        __stcs(reinterpret_cast<float4*>(&g_wL_part[seg][2 * kp][cw]),     lo);
        __stcs(reinterpret_cast<float4*>(&g_wL_part[seg][2 * kp + 1][cw]), hi);
    }
}

// ============================================================
// k1b: reduce 16 partial segments into g_wL. 32768 float2 threads.
// ============================================================
__global__ __launch_bounds__(128, 1) void k1_reduce() {
    int i = blockIdx.x * 128 + threadIdx.x;           // float2 index, 32768 total
    const float2* base = reinterpret_cast<const float2*>(&g_wL_part[0][0][0]);
    const int seg_stride = KF * N_SIMP / 2;           // 32768 float2 per segment
    float2 s = make_float2(0.f, 0.f);
    #pragma unroll
    for (int pb = 0; pb < SEG1; pb += 8) {
        float2 v[8];
        #pragma unroll
        for (int r = 0; r < 8; r++)
            v[r] = __ldcs(&base[(size_t)(pb + r) * seg_stride + i]);
        #pragma unroll
        for (int r = 0; r < 8; r++) { s.x += v[r].x; s.y += v[r].y; }
    }
    reinterpret_cast<float2*>(&g_wL[0][0])[i] = s;
}

// ============================================================
// k2: partial out accumulation. Block = (b, seg), 512 CTAs.
// cp.async 4-stage pipeline: stage = 8 x rows (contiguous 4 KB).
// 128 threads = 32 f-groups x 4 n-subgroups; each thread handles
// rows {ng, ng+4} of each stage. Epilogue: smem tree-reduce over ng.
// ============================================================
__global__ __launch_bounds__(128, 4) void k2_out(const float* __restrict__ x) {
    const int tid = threadIdx.x;
    const int fg  = tid & 31;
    const int ng  = tid >> 5;
    const int b   = blockIdx.x;
    const int seg = blockIdx.y;
    const int n0  = seg * ROWS2;

    __shared__ float2 wlp[4][ROWS2];           // 32 KB, k-pairs of wL
    __shared__ float4 stg2[DEPTH][S2 * 32];    // 16 KB (4 stages x 4 KB)

    for (int idx = tid; idx < 4 * ROWS2; idx += 128) {
        int kp = idx >> 10;
        int n  = idx & (ROWS2 - 1);
        wlp[kp][n] = make_float2(g_wL[2 * kp][n0 + n], g_wL[2 * kp + 1][n0 + n]);
    }

    const float*   xb  = x + ((size_t)b * N_SIMP + n0) * FEAT;
    const uint32_t st0 = smem_u32(&stg2[0][0]);

    auto issue = [&](int s) {
        if (s < NST2) {
            int buf = s & (DEPTH - 1);
            uint32_t d = st0 + buf * 4096 + tid * 16;
            const float* g = xb + (size_t)s * (S2 * FEAT) + tid * 4;
            cp16(d,        g);
            cp16(d + 2048, g + 512);
        }
        CP_COMMIT();
    };

    issue(0); issue(1); issue(2);

    ull acc[4][4];
    #pragma unroll
    for (int kp = 0; kp < 4; kp++)
        #pragma unroll
        for (int j = 0; j < 4; j++) acc[kp][j] = 0ULL;

    for (int s = 0; s < NST2; s++) {
        CP_WAIT2();
        __syncthreads();
        issue(s + DEPTH - 1);
        const int buf = s & (DEPTH - 1);
        #pragma unroll
        for (int rr = 0; rr < 2; rr++) {
            const int r = ng + rr * 4;
            float4 xv = stg2[buf][r * 32 + fg];   // LDS.128, conflict-free
            ull xd[4] = { pack_dup(xv.x), pack_dup(xv.y),
                          pack_dup(xv.z), pack_dup(xv.w) };
            const int n = s * S2 + r;
            #pragma unroll
            for (int kp = 0; kp < 4; kp++) {
                ull wp = *reinterpret_cast<const ull*>(&wlp[kp][n]);   // LDS.64 bcast
                #pragma unroll
                for (int j = 0; j < 4; j++) fma2(acc[kp][j], xd[j], wp);
            }
        }
    }

    // ---- epilogue: reduce over the 4 n-subgroups via smem (2 rounds) ----
    __syncthreads();
    float (*rbuf)[32][32] = reinterpret_cast<float (*)[32][32]>(&wlp[0][0]);

    float mine[32];
    #pragma unroll
    for (int kp = 0; kp < 4; kp++) {
        #pragma unroll
        for (int j = 0; j < 4; j++) {
            float2 v = unpack2(acc[kp][j]);
            mine[(2 * kp) * 4 + j]     = v.x;
            mine[(2 * kp + 1) * 4 + j] = v.y;
        }
    }

    if (ng >= 2) {
        #pragma unroll
        for (int t = 0; t < 32; t++) rbuf[ng - 2][fg][t] = mine[t];
    }
    __syncthreads();
    if (ng < 2) {
        #pragma unroll
        for (int t = 0; t < 32; t++) mine[t] += rbuf[ng][fg][t];
    }
    __syncthreads();
    if (ng == 1) {
        #pragma unroll
        for (int t = 0; t < 32; t++) rbuf[0][fg][t] = mine[t];
    }
    __syncthreads();
    if (ng == 0) {
        #pragma unroll
        for (int k = 0; k < 8; k++) {
            float4 o = make_float4(mine[k * 4 + 0] + rbuf[0][fg][k * 4 + 0],
                                   mine[k * 4 + 1] + rbuf[0][fg][k * 4 + 1],
                                   mine[k * 4 + 2] + rbuf[0][fg][k * 4 + 2],
                                   mine[k * 4 + 3] + rbuf[0][fg][k * 4 + 3]);
            __stcs(reinterpret_cast<float4*>(&g_acc_part[seg][k][b][fg * 4]), o);
        }
    }
}

// ============================================================
// k3: reduce 8 partials + tanh -> out [K, B, F]. 32768 float2 threads.
// ============================================================
__global__ __launch_bounds__(128, 1) void k3_tanh(float* __restrict__ out) {
    int i = blockIdx.x * 128 + threadIdx.x;           // float2 index, 32768 total
    const float2* base = reinterpret_cast<const float2*>(&g_acc_part[0][0][0][0]);
    const int part_stride = KF * BATCH * FEAT / 2;    // 32768 float2 per partial
    float2 v[SEG2];
    #pragma unroll
    for (int r = 0; r < SEG2; r++)
        v[r] = __ldcs(&base[(size_t)r * part_stride + i]);
    float2 s = make_float2(0.f, 0.f);
    #pragma unroll
    for (int r = 0; r < SEG2; r++) { s.x += v[r].x; s.y += v[r].y; }
    reinterpret_cast<float2*>(out)[i] = make_float2(tanhf(s.x), tanhf(s.y));
}

// ============================================================
extern "C" void kernel_launch(void* const* d_in, const int* in_sizes, int n_in,
                              void* d_out, int out_size) {
    const float* x = (const float*)d_in[0];   // [B, N, F]
    const float* L = (const float*)d_in[1];   // [N, N]
    const float* W = (const float*)d_in[2];   // [K, N]
    float* out = (float*)d_out;               // [K, B, F]

    k1_wl<<<dim3(COLB1, SEG1), 128>>>(W, L);
    k1_reduce<<<256, 128>>>();
    k2_out<<<dim3(BATCH, SEG2), 128>>>(x);
    k3_tanh<<<256, 128>>>(out);
}